// round 12
// baseline (speedup 1.0000x reference)
#include <cuda_runtime.h>
#include <cuda_bf16.h>
#include <cuda_fp16.h>
#include <mma.h>
#include <math.h>

using namespace nvcuda;

#define NN 50000
#define NNP 50048            // padded to multiple of 128 for WMMA tiles
#define NE 800000
#define NT (NE + NN)
#define FIN 128
#define F1 256
#define H1HEADS 4
#define F2 64
#define NEG_SLOPE 0.2f

// -------- scratch (device globals; zero-initialized at load) --------
__device__ __half g_xh[NNP * FIN];     // fp16 input features (pad rows stay 0)
__device__ __half g_w1h[FIN * F1];
__device__ __half g_w2h[F1 * F2];
__device__ __half g_h1h[NNP * F1];     // layer1 features, fp16 (GEMM1 out)
__device__ __half g_out1h[NNP * F1];   // relu(gat1) fp16 (GEMM2 in; pads stay 0)
__device__ __half g_h2h[NNP * F2];     // layer2 features, fp16 (GEMM2 out)
__device__ float  g_as1[NN * H1HEADS];
__device__ float  g_ad1[NN * H1HEADS];
__device__ float  g_as2[NN];
__device__ float  g_ad2[NN];
__device__ float  g_p1[(long long)NT * 4];   // per-(edge,head) softmax numerators
__device__ float  g_den1[NN * 4];
__device__ float  g_p2[NT];
__device__ float  g_den2[NN];
__device__ int    g_deg[NN];
__device__ int    g_rowptr[NN + 1];
__device__ int    g_fill[NN];
__device__ int    g_csrsrc[NT];

__device__ __forceinline__ float lrelu(float x) {
    return x > 0.f ? x : NEG_SLOPE * x;
}

// ------- prep: convert x/W1/W2 to fp16 + init deg, all in one kernel -------
#define R0 (NN * FIN / 4)
#define R1 (FIN * F1 / 4)
#define R2 (F1 * F2 / 4)
#define RTOT (R0 + R1 + R2 + NN)

__device__ __forceinline__ void cvt4(const float* src, __half* dst, int i4) {
    float4 v = *(const float4*)&src[i4];
    __half2 h0 = __floats2half2_rn(v.x, v.y);
    __half2 h1 = __floats2half2_rn(v.z, v.w);
    uint2 u;
    u.x = *(unsigned int*)&h0;
    u.y = *(unsigned int*)&h1;
    *(uint2*)&dst[i4] = u;
}

__global__ void k_prep(const float* __restrict__ x, const float* __restrict__ W1,
                       const float* __restrict__ W2) {
    int i = blockIdx.x * blockDim.x + threadIdx.x;
    if (i < R0) cvt4(x, g_xh, i * 4);
    else if (i < R0 + R1) cvt4(W1, g_w1h, (i - R0) * 4);
    else if (i < R0 + R1 + R2) cvt4(W2, g_w2h, (i - R0 - R1) * 4);
    else if (i < RTOT) g_deg[i - R0 - R1 - R2] = 1;   // self loop
}

// ---------------- CSR build ----------------
__global__ void k_count(const int* __restrict__ edge) {
    int e = blockIdx.x * blockDim.x + threadIdx.x;
    if (e < NE) atomicAdd(&g_deg[edge[NE + e]], 1);
}

// one-pass block scan: 1024 threads, 49 contiguous elems each
__global__ __launch_bounds__(1024) void k_scan() {
    const int t = threadIdx.x;
    const int CH = (NN + 1023) / 1024;   // 49
    int lo = t * CH, hi = min(lo + CH, NN);
    int sum = 0;
    for (int i = lo; i < hi; i++) sum += g_deg[i];

    int lane = t & 31, warp = t >> 5;
    int incl = sum;
    #pragma unroll
    for (int o = 1; o < 32; o <<= 1) {
        int u = __shfl_up_sync(0xffffffffu, incl, o);
        if (lane >= o) incl += u;
    }
    __shared__ int wsum[32];
    if (lane == 31) wsum[warp] = incl;
    __syncthreads();
    if (t < 32) {
        int v = wsum[t];
        int iv = v;
        #pragma unroll
        for (int o = 1; o < 32; o <<= 1) {
            int u = __shfl_up_sync(0xffffffffu, iv, o);
            if (t >= o) iv += u;
        }
        wsum[t] = iv - v;   // exclusive warp prefix
    }
    __syncthreads();
    int run = wsum[warp] + (incl - sum);
    for (int i = lo; i < hi; i++) {
        g_rowptr[i] = run;
        g_fill[i] = run;
        run += g_deg[i];
    }
    if (t == 1023) g_rowptr[NN] = run;
}

__global__ void k_scatter(const int* __restrict__ edge) {
    int t = blockIdx.x * blockDim.x + threadIdx.x;
    if (t < NE) {
        int d = edge[NE + t];
        int s = edge[t];
        int pos = atomicAdd(&g_fill[d], 1);
        g_csrsrc[pos] = s;
    } else if (t < NT) {
        int i = t - NE;
        int pos = atomicAdd(&g_fill[i], 1);
        g_csrsrc[pos] = i;
    }
}

// -------- WMMA GEMM1: g_h1h[NNP,256] = g_xh[NNP,128] @ g_w1h[128,256] --------
__global__ __launch_bounds__(256)
void hgemm1_kernel() {
    __shared__ __align__(16) char smem[69632];
    __half (*As)[136] = reinterpret_cast<__half(*)[136]>(smem);
    __half (*Bs)[136] = reinterpret_cast<__half(*)[136]>(smem + 34816);
    float (*Cs)[132] = reinterpret_cast<float(*)[132]>(smem);
    const int tx = threadIdx.x;
    const int rowBase = blockIdx.x * 128;
    const int colBase = blockIdx.y * 128;

    for (int c = tx; c < 128 * 16; c += 256) {
        int r = c >> 4, c8 = (c & 15) << 3;
        *(uint4*)&As[r][c8] = *(const uint4*)&g_xh[(size_t)(rowBase + r) * FIN + c8];
    }
    for (int c = tx; c < 128 * 16; c += 256) {
        int r = c >> 4, c8 = (c & 15) << 3;
        *(uint4*)&Bs[r][c8] = *(const uint4*)&g_w1h[(size_t)r * F1 + colBase + c8];
    }
    __syncthreads();

    const int warp = tx >> 5;
    const int wm = warp >> 1;
    const int wn = warp & 1;
    wmma::fragment<wmma::accumulator, 16, 16, 16, float> acc[2][4];
    #pragma unroll
    for (int i = 0; i < 2; i++)
        #pragma unroll
        for (int j = 0; j < 4; j++) wmma::fill_fragment(acc[i][j], 0.f);

    #pragma unroll
    for (int k0 = 0; k0 < FIN; k0 += 16) {
        wmma::fragment<wmma::matrix_a, 16, 16, 16, __half, wmma::row_major> af[2];
        wmma::fragment<wmma::matrix_b, 16, 16, 16, __half, wmma::row_major> bf[4];
        #pragma unroll
        for (int i = 0; i < 2; i++)
            wmma::load_matrix_sync(af[i], &As[wm * 32 + i * 16][k0], 136);
        #pragma unroll
        for (int j = 0; j < 4; j++)
            wmma::load_matrix_sync(bf[j], &Bs[k0][wn * 64 + j * 16], 136);
        #pragma unroll
        for (int i = 0; i < 2; i++)
            #pragma unroll
            for (int j = 0; j < 4; j++)
                wmma::mma_sync(acc[i][j], af[i], bf[j], acc[i][j]);
    }
    __syncthreads();
    #pragma unroll
    for (int i = 0; i < 2; i++)
        #pragma unroll
        for (int j = 0; j < 4; j++)
            wmma::store_matrix_sync(&Cs[wm * 32 + i * 16][wn * 64 + j * 16],
                                    acc[i][j], 132, wmma::mem_row_major);
    __syncthreads();
    for (int c = tx; c < 128 * 32; c += 256) {
        int r = c >> 5, c4 = (c & 31) << 2;
        float4 v = *(float4*)&Cs[r][c4];
        __half2 h0 = __floats2half2_rn(v.x, v.y);
        __half2 h1 = __floats2half2_rn(v.z, v.w);
        uint2 u;
        u.x = *(unsigned int*)&h0;
        u.y = *(unsigned int*)&h1;
        *(uint2*)&g_h1h[(size_t)(rowBase + r) * F1 + colBase + c4] = u;
    }
}

// -------- WMMA GEMM2: g_h2h[NNP,64] = g_out1h[NNP,256] @ g_w2h[256,64] -------
__global__ __launch_bounds__(256)
void hgemm2_kernel() {
    __shared__ __align__(16) char smem[53248];
    __half (*As)[136] = reinterpret_cast<__half(*)[136]>(smem);
    __half (*Bs)[72] = reinterpret_cast<__half(*)[72]>(smem + 34816);
    float (*Cs)[68] = reinterpret_cast<float(*)[68]>(smem);
    const int tx = threadIdx.x;
    const int rowBase = blockIdx.x * 128;

    const int warp = tx >> 5;
    const int wm = warp >> 1;
    const int wn = warp & 1;
    wmma::fragment<wmma::accumulator, 16, 16, 16, float> acc[2][2];
    #pragma unroll
    for (int i = 0; i < 2; i++)
        #pragma unroll
        for (int j = 0; j < 2; j++) wmma::fill_fragment(acc[i][j], 0.f);

    for (int t = 0; t < 2; t++) {
        const int kBase = t * 128;
        for (int c = tx; c < 128 * 16; c += 256) {
            int r = c >> 4, c8 = (c & 15) << 3;
            *(uint4*)&As[r][c8] =
                *(const uint4*)&g_out1h[(size_t)(rowBase + r) * F1 + kBase + c8];
        }
        for (int c = tx; c < 128 * 8; c += 256) {
            int r = c >> 3, c8 = (c & 7) << 3;
            *(uint4*)&Bs[r][c8] = *(const uint4*)&g_w2h[(size_t)(kBase + r) * F2 + c8];
        }
        __syncthreads();
        #pragma unroll
        for (int k0 = 0; k0 < 128; k0 += 16) {
            wmma::fragment<wmma::matrix_a, 16, 16, 16, __half, wmma::row_major> af[2];
            wmma::fragment<wmma::matrix_b, 16, 16, 16, __half, wmma::row_major> bf[2];
            #pragma unroll
            for (int i = 0; i < 2; i++)
                wmma::load_matrix_sync(af[i], &As[wm * 32 + i * 16][k0], 136);
            #pragma unroll
            for (int j = 0; j < 2; j++)
                wmma::load_matrix_sync(bf[j], &Bs[k0][wn * 32 + j * 16], 72);
            #pragma unroll
            for (int i = 0; i < 2; i++)
                #pragma unroll
                for (int j = 0; j < 2; j++)
                    wmma::mma_sync(acc[i][j], af[i], bf[j], acc[i][j]);
        }
        __syncthreads();
    }
    #pragma unroll
    for (int i = 0; i < 2; i++)
        #pragma unroll
        for (int j = 0; j < 2; j++)
            wmma::store_matrix_sync(&Cs[wm * 32 + i * 16][wn * 32 + j * 16],
                                    acc[i][j], 68, wmma::mem_row_major);
    __syncthreads();
    for (int c = tx; c < 128 * 16; c += 256) {
        int r = c >> 4, c4 = (c & 15) << 2;
        float4 v = *(float4*)&Cs[r][c4];
        __half2 h0 = __floats2half2_rn(v.x, v.y);
        __half2 h1 = __floats2half2_rn(v.z, v.w);
        uint2 u;
        u.x = *(unsigned int*)&h0;
        u.y = *(unsigned int*)&h1;
        *(uint2*)&g_h2h[(size_t)(rowBase + r) * F2 + c4] = u;
    }
}

// ---------------- alpha projections (read fp16 features) ----------------
__global__ void alpha1_kernel(const float* __restrict__ a_src,
                              const float* __restrict__ a_dst) {
    int warp = threadIdx.x >> 5, lane = threadIdx.x & 31;
    int node = blockIdx.x * 2 + (warp >> 2);
    int h = warp & 3;
    if (node >= NN) return;
    const __half2* row = (const __half2*)(g_h1h + (size_t)node * F1 + h * 64);
    float2 f = __half22float2(row[lane]);
    float s = f.x * a_src[h * 64 + lane * 2] + f.y * a_src[h * 64 + lane * 2 + 1];
    float d = f.x * a_dst[h * 64 + lane * 2] + f.y * a_dst[h * 64 + lane * 2 + 1];
    #pragma unroll
    for (int o = 16; o > 0; o >>= 1) {
        s += __shfl_down_sync(0xffffffffu, s, o);
        d += __shfl_down_sync(0xffffffffu, d, o);
    }
    if (lane == 0) { g_as1[node * 4 + h] = s; g_ad1[node * 4 + h] = d; }
}

__global__ void alpha2_kernel(const float* __restrict__ a_src,
                              const float* __restrict__ a_dst) {
    int warp = threadIdx.x >> 5, lane = threadIdx.x & 31;
    int node = blockIdx.x * 8 + warp;
    if (node >= NN) return;
    const __half2* row = (const __half2*)(g_h2h + (size_t)node * F2);
    float2 f = __half22float2(row[lane]);
    float s = f.x * a_src[lane * 2] + f.y * a_src[lane * 2 + 1];
    float d = f.x * a_dst[lane * 2] + f.y * a_dst[lane * 2 + 1];
    #pragma unroll
    for (int o = 16; o > 0; o >>= 1) {
        s += __shfl_down_sync(0xffffffffu, s, o);
        d += __shfl_down_sync(0xffffffffu, d, o);
    }
    if (lane == 0) { g_as2[node] = s; g_ad2[node] = d; }
}

// ---------- edge softmax layer 1: one warp per dst, 4 heads x 8 lanes ----------
__global__ __launch_bounds__(256)
void escore1_kernel() {
    int w = (blockIdx.x * blockDim.x + threadIdx.x) >> 5;
    if (w >= NN) return;
    int lane = threadIdx.x & 31;
    int h = lane >> 3, sl = lane & 7;
    int beg = g_rowptr[w], end = g_rowptr[w + 1];
    float adv = g_ad1[w * 4 + h];

    float m = -1e30f;
    for (int i = beg + sl; i < end; i += 8)
        m = fmaxf(m, lrelu(g_as1[g_csrsrc[i] * 4 + h] + adv));
    #pragma unroll
    for (int o = 4; o > 0; o >>= 1)
        m = fmaxf(m, __shfl_xor_sync(0xffffffffu, m, o, 8));

    float den = 0.f;
    for (int i = beg + sl; i < end; i += 8) {
        float p = __expf(lrelu(g_as1[g_csrsrc[i] * 4 + h] + adv) - m);
        den += p;
        g_p1[(long long)i * 4 + h] = p;
    }
    #pragma unroll
    for (int o = 4; o > 0; o >>= 1)
        den += __shfl_xor_sync(0xffffffffu, den, o, 8);
    if (sl == 0) g_den1[w * 4 + h] = den;
}

// ---------- edge softmax layer 2: one warp per dst ----------
__global__ __launch_bounds__(256)
void escore2_kernel() {
    int w = (blockIdx.x * blockDim.x + threadIdx.x) >> 5;
    if (w >= NN) return;
    int lane = threadIdx.x & 31;
    int beg = g_rowptr[w], end = g_rowptr[w + 1];
    float adv = g_ad2[w];

    float m = -1e30f;
    for (int i = beg + lane; i < end; i += 32)
        m = fmaxf(m, lrelu(g_as2[g_csrsrc[i]] + adv));
    #pragma unroll
    for (int o = 16; o > 0; o >>= 1)
        m = fmaxf(m, __shfl_xor_sync(0xffffffffu, m, o));

    float den = 0.f;
    for (int i = beg + lane; i < end; i += 32) {
        float p = __expf(lrelu(g_as2[g_csrsrc[i]] + adv) - m);
        den += p;
        g_p2[i] = p;
    }
    #pragma unroll
    for (int o = 16; o > 0; o >>= 1)
        den += __shfl_xor_sync(0xffffffffu, den, o);
    if (lane == 0) g_den2[w] = den;
}

// ------- layer 1 aggregation: pure gather+fma (p precomputed), 64 thr/dst -----
__global__ __launch_bounds__(64)
void agg1_kernel(const float* __restrict__ b1) {
    int d = blockIdx.x;
    int t = threadIdx.x;
    int h = t >> 4;
    int beg = g_rowptr[d], end = g_rowptr[d + 1];
    float inv = 1.f / (g_den1[d * 4 + h] + 1e-16f);

    const uint2* __restrict__ h1v = (const uint2*)g_h1h;
    float ax = 0.f, ay = 0.f, az = 0.f, aw = 0.f;
    int i = beg;
    for (; i + 1 < end; i += 2) {
        int s0 = g_csrsrc[i], s1 = g_csrsrc[i + 1];
        float p0 = g_p1[(long long)i * 4 + h];
        float p1 = g_p1[(long long)(i + 1) * 4 + h];
        uint2 r0 = h1v[(size_t)s0 * 64 + t];
        uint2 r1 = h1v[(size_t)s1 * 64 + t];
        float2 f0a = __half22float2(*(__half2*)&r0.x);
        float2 f0b = __half22float2(*(__half2*)&r0.y);
        float2 f1a = __half22float2(*(__half2*)&r1.x);
        float2 f1b = __half22float2(*(__half2*)&r1.y);
        ax = fmaf(p0, f0a.x, ax); ax = fmaf(p1, f1a.x, ax);
        ay = fmaf(p0, f0a.y, ay); ay = fmaf(p1, f1a.y, ay);
        az = fmaf(p0, f0b.x, az); az = fmaf(p1, f1b.x, az);
        aw = fmaf(p0, f0b.y, aw); aw = fmaf(p1, f1b.y, aw);
    }
    if (i < end) {
        int s0 = g_csrsrc[i];
        float p0 = g_p1[(long long)i * 4 + h];
        uint2 r0 = h1v[(size_t)s0 * 64 + t];
        float2 f0a = __half22float2(*(__half2*)&r0.x);
        float2 f0b = __half22float2(*(__half2*)&r0.y);
        ax = fmaf(p0, f0a.x, ax); ay = fmaf(p0, f0a.y, ay);
        az = fmaf(p0, f0b.x, az); aw = fmaf(p0, f0b.y, aw);
    }
    float4 bv = ((const float4*)b1)[t];
    float ox = fmaxf(ax * inv + bv.x, 0.f);
    float oy = fmaxf(ay * inv + bv.y, 0.f);
    float oz = fmaxf(az * inv + bv.z, 0.f);
    float ow = fmaxf(aw * inv + bv.w, 0.f);
    __half2 ha = __floats2half2_rn(ox, oy);
    __half2 hb = __floats2half2_rn(oz, ow);
    uint2 u;
    u.x = *(unsigned int*)&ha;
    u.y = *(unsigned int*)&hb;
    ((uint2*)g_out1h)[(size_t)d * 64 + t] = u;
}

// ------- layer 2 aggregation: pure gather+fma, 4 dsts per 64-thread block -----
__global__ __launch_bounds__(64)
void agg2_kernel(const float* __restrict__ b2, float* __restrict__ out) {
    int t = threadIdx.x;
    int g = t >> 4;
    int l = t & 15;
    int d = blockIdx.x * 4 + g;
    if (d >= NN) return;
    int beg = g_rowptr[d], end = g_rowptr[d + 1];
    float inv = 1.f / (g_den2[d] + 1e-16f);

    const uint2* __restrict__ h2v = (const uint2*)g_h2h;
    float ax = 0.f, ay = 0.f, az = 0.f, aw = 0.f;
    int i = beg;
    for (; i + 1 < end; i += 2) {
        int s0 = g_csrsrc[i], s1 = g_csrsrc[i + 1];
        float p0 = g_p2[i], p1 = g_p2[i + 1];
        uint2 r0 = h2v[(size_t)s0 * 16 + l];
        uint2 r1 = h2v[(size_t)s1 * 16 + l];
        float2 f0a = __half22float2(*(__half2*)&r0.x);
        float2 f0b = __half22float2(*(__half2*)&r0.y);
        float2 f1a = __half22float2(*(__half2*)&r1.x);
        float2 f1b = __half22float2(*(__half2*)&r1.y);
        ax = fmaf(p0, f0a.x, ax); ax = fmaf(p1, f1a.x, ax);
        ay = fmaf(p0, f0a.y, ay); ay = fmaf(p1, f1a.y, ay);
        az = fmaf(p0, f0b.x, az); az = fmaf(p1, f1b.x, az);
        aw = fmaf(p0, f0b.y, aw); aw = fmaf(p1, f1b.y, aw);
    }
    if (i < end) {
        int s0 = g_csrsrc[i];
        float p0 = g_p2[i];
        uint2 r0 = h2v[(size_t)s0 * 16 + l];
        float2 f0a = __half22float2(*(__half2*)&r0.x);
        float2 f0b = __half22float2(*(__half2*)&r0.y);
        ax = fmaf(p0, f0a.x, ax); ay = fmaf(p0, f0a.y, ay);
        az = fmaf(p0, f0b.x, az); aw = fmaf(p0, f0b.y, aw);
    }
    float4 bv = ((const float4*)b2)[l];
    float4 o;
    o.x = ax * inv + bv.x;
    o.y = ay * inv + bv.y;
    o.z = az * inv + bv.z;
    o.w = aw * inv + bv.w;
    ((float4*)out)[(size_t)d * 16 + l] = o;
}

// ---------------- launch (12 kernels) ----------------
extern "C" void kernel_launch(void* const* d_in, const int* in_sizes, int n_in,
                              void* d_out, int out_size) {
    const float* x      = (const float*)d_in[0];
    const int*   edge   = (const int*)d_in[1];   // int32 (JAX x64 disabled)
    const float* W1     = (const float*)d_in[2];
    const float* a_src1 = (const float*)d_in[3];
    const float* a_dst1 = (const float*)d_in[4];
    const float* b1     = (const float*)d_in[5];
    const float* W2     = (const float*)d_in[6];
    const float* a_src2 = (const float*)d_in[7];
    const float* a_dst2 = (const float*)d_in[8];
    const float* b2     = (const float*)d_in[9];
    float* out = (float*)d_out;

    k_prep<<<(RTOT + 255) / 256, 256>>>(x, W1, W2);          // idx 0
    k_count<<<(NE + 255) / 256, 256>>>(edge);                // idx 1
    k_scan<<<1, 1024>>>();                                   // idx 2

    // idx 3: GEMM1 (profiled slot)
    {
        dim3 grid(NNP / 128, F1 / 128);
        hgemm1_kernel<<<grid, 256>>>();
    }

    k_scatter<<<(NT + 255) / 256, 256>>>(edge);              // idx 4
    alpha1_kernel<<<(NN + 1) / 2, 256>>>(a_src1, a_dst1);    // idx 5
    escore1_kernel<<<(NN * 32 + 255) / 256, 256>>>();        // idx 6
    agg1_kernel<<<NN, 64>>>(b1);                             // idx 7
    hgemm2_kernel<<<NNP / 128, 256>>>();                     // idx 8
    alpha2_kernel<<<(NN + 7) / 8, 256>>>(a_src2, a_dst2);    // idx 9
    escore2_kernel<<<(NN * 32 + 255) / 256, 256>>>();        // idx 10
    agg2_kernel<<<(NN + 3) / 4, 64>>>(b2, out);              // idx 11
}

// round 13
// speedup vs baseline: 1.9068x; 1.9068x over previous
#include <cuda_runtime.h>
#include <cuda_bf16.h>
#include <cuda_fp16.h>
#include <mma.h>
#include <math.h>

using namespace nvcuda;

#define NN 50000
#define NNP 50048            // padded to multiple of 128 for WMMA tiles
#define NE 800000
#define NT (NE + NN)
#define FIN 128
#define F1 256
#define H1HEADS 4
#define F2 64
#define NEG_SLOPE 0.2f
#define NBLK 49              // ceil(NN/1024)

// -------- scratch (device globals; zero-initialized at load) --------
__device__ __half g_xh[NNP * FIN];
__device__ __half g_w1h[FIN * F1];
__device__ __half g_w2h[F1 * F2];
__device__ __half g_h1h[NNP * F1];     // layer1 features fp16 (gather source)
__device__ __half g_out1h[NNP * F1];   // relu(gat1) fp16 (GEMM2 in; pads stay 0)
__device__ __half g_h2h[NNP * F2];
__device__ float  g_as1[NN * H1HEADS];
__device__ float  g_ad1[NN * H1HEADS];
__device__ float  g_as2[NN];
__device__ float  g_ad2[NN];
__device__ float  g_p1[(long long)NT * 4];
__device__ float  g_den1[NN * 4];
__device__ float  g_p2[NT];
__device__ float  g_den2[NN];
__device__ int    g_deg[NN];
__device__ int    g_bsum[64];
__device__ int    g_boff[64];
__device__ int    g_rowptr[NN + 1];
__device__ int    g_fill[NN];
__device__ int    g_csrsrc[NT];

__device__ __forceinline__ float lrelu(float x) {
    return x > 0.f ? x : NEG_SLOPE * x;
}

// ------- prep: convert x/W1/W2 to fp16 + init deg -------
#define R0 (NN * FIN / 4)
#define R1 (FIN * F1 / 4)
#define R2 (F1 * F2 / 4)
#define RTOT (R0 + R1 + R2 + NN)

__device__ __forceinline__ void cvt4(const float* src, __half* dst, int i4) {
    float4 v = *(const float4*)&src[i4];
    __half2 h0 = __floats2half2_rn(v.x, v.y);
    __half2 h1 = __floats2half2_rn(v.z, v.w);
    uint2 u;
    u.x = *(unsigned int*)&h0;
    u.y = *(unsigned int*)&h1;
    *(uint2*)&dst[i4] = u;
}

__global__ void k_prep(const float* __restrict__ x, const float* __restrict__ W1,
                       const float* __restrict__ W2) {
    int i = blockIdx.x * blockDim.x + threadIdx.x;
    if (i < R0) cvt4(x, g_xh, i * 4);
    else if (i < R0 + R1) cvt4(W1, g_w1h, (i - R0) * 4);
    else if (i < R0 + R1 + R2) cvt4(W2, g_w2h, (i - R0 - R1) * 4);
    else if (i < RTOT) g_deg[i - R0 - R1 - R2] = 1;   // self loop
}

__global__ void k_count(const int* __restrict__ edge) {
    int e = blockIdx.x * blockDim.x + threadIdx.x;
    if (e < NE) atomicAdd(&g_deg[edge[NE + e]], 1);
}

// ---- scan phase A: per-block partial sums (49 blocks x 1024) ----
__global__ __launch_bounds__(1024) void k_scan_a() {
    int t = threadIdx.x;
    int idx = blockIdx.x * 1024 + t;
    int v = (idx < NN) ? g_deg[idx] : 0;
    int lane = t & 31, warp = t >> 5;
    #pragma unroll
    for (int o = 16; o > 0; o >>= 1) v += __shfl_xor_sync(0xffffffffu, v, o);
    __shared__ int ws[32];
    if (lane == 0) ws[warp] = v;
    __syncthreads();
    if (t < 32) {
        int u = ws[t];
        #pragma unroll
        for (int o = 16; o > 0; o >>= 1) u += __shfl_xor_sync(0xffffffffu, u, o);
        if (t == 0) g_bsum[blockIdx.x] = u;
    }
}

// ---- scan phase B: one warp scans the 49 partials ----
__global__ void k_scan_b() {
    int lane = threadIdx.x;   // 32 threads
    int v0 = (lane < NBLK) ? g_bsum[lane] : 0;
    int v1 = (lane + 32 < NBLK) ? g_bsum[lane + 32] : 0;
    int s0 = v0;
    #pragma unroll
    for (int o = 1; o < 32; o <<= 1) {
        int u = __shfl_up_sync(0xffffffffu, s0, o);
        if (lane >= o) s0 += u;
    }
    int tot0 = __shfl_sync(0xffffffffu, s0, 31);
    int s1 = v1;
    #pragma unroll
    for (int o = 1; o < 32; o <<= 1) {
        int u = __shfl_up_sync(0xffffffffu, s1, o);
        if (lane >= o) s1 += u;
    }
    if (lane < NBLK) g_boff[lane] = s0 - v0;
    if (lane + 32 < NBLK) g_boff[lane + 32] = tot0 + s1 - v1;
    if (lane == 31) g_rowptr[NN] = tot0 + __shfl_sync(0xffffffffu, s1, 31);
}

// ---- scan phase C: write rowptr/fill (49 blocks x 1024) ----
__global__ __launch_bounds__(1024) void k_scan_c() {
    int t = threadIdx.x;
    int idx = blockIdx.x * 1024 + t;
    int v = (idx < NN) ? g_deg[idx] : 0;
    int lane = t & 31, warp = t >> 5;
    int incl = v;
    #pragma unroll
    for (int o = 1; o < 32; o <<= 1) {
        int u = __shfl_up_sync(0xffffffffu, incl, o);
        if (lane >= o) incl += u;
    }
    __shared__ int ws[32];
    if (lane == 31) ws[warp] = incl;
    __syncthreads();
    if (t < 32) {
        int u = ws[t];
        int iv = u;
        #pragma unroll
        for (int o = 1; o < 32; o <<= 1) {
            int w = __shfl_up_sync(0xffffffffu, iv, o);
            if (t >= o) iv += w;
        }
        ws[t] = iv - u;
    }
    __syncthreads();
    if (idx < NN) {
        int excl = g_boff[blockIdx.x] + ws[warp] + incl - v;
        g_rowptr[idx] = excl;
        g_fill[idx] = excl;
    }
}

__global__ void k_scatter(const int* __restrict__ edge) {
    int t = blockIdx.x * blockDim.x + threadIdx.x;
    if (t < NE) {
        int d = edge[NE + t];
        int s = edge[t];
        int pos = atomicAdd(&g_fill[d], 1);
        g_csrsrc[pos] = s;
    } else if (t < NT) {
        int i = t - NE;
        int pos = atomicAdd(&g_fill[i], 1);
        g_csrsrc[pos] = i;
    }
}

// -------- WMMA GEMM1 + fused alpha1: fp16 store + as1/ad1 from fp32 tile -----
__global__ __launch_bounds__(256)
void hgemm1_kernel(const float* __restrict__ a_src, const float* __restrict__ a_dst) {
    __shared__ __align__(16) char smem[69632];
    __half (*As)[136] = reinterpret_cast<__half(*)[136]>(smem);
    __half (*Bs)[136] = reinterpret_cast<__half(*)[136]>(smem + 34816);
    float (*Cs)[132] = reinterpret_cast<float(*)[132]>(smem);
    const int tx = threadIdx.x;
    const int rowBase = blockIdx.x * 128;
    const int colBase = blockIdx.y * 128;

    for (int c = tx; c < 128 * 16; c += 256) {
        int r = c >> 4, c8 = (c & 15) << 3;
        *(uint4*)&As[r][c8] = *(const uint4*)&g_xh[(size_t)(rowBase + r) * FIN + c8];
    }
    for (int c = tx; c < 128 * 16; c += 256) {
        int r = c >> 4, c8 = (c & 15) << 3;
        *(uint4*)&Bs[r][c8] = *(const uint4*)&g_w1h[(size_t)r * F1 + colBase + c8];
    }
    __syncthreads();

    const int warp = tx >> 5;
    const int wm = warp >> 1;
    const int wn = warp & 1;
    wmma::fragment<wmma::accumulator, 16, 16, 16, float> acc[2][4];
    #pragma unroll
    for (int i = 0; i < 2; i++)
        #pragma unroll
        for (int j = 0; j < 4; j++) wmma::fill_fragment(acc[i][j], 0.f);

    #pragma unroll
    for (int k0 = 0; k0 < FIN; k0 += 16) {
        wmma::fragment<wmma::matrix_a, 16, 16, 16, __half, wmma::row_major> af[2];
        wmma::fragment<wmma::matrix_b, 16, 16, 16, __half, wmma::row_major> bf[4];
        #pragma unroll
        for (int i = 0; i < 2; i++)
            wmma::load_matrix_sync(af[i], &As[wm * 32 + i * 16][k0], 136);
        #pragma unroll
        for (int j = 0; j < 4; j++)
            wmma::load_matrix_sync(bf[j], &Bs[k0][wn * 64 + j * 16], 136);
        #pragma unroll
        for (int i = 0; i < 2; i++)
            #pragma unroll
            for (int j = 0; j < 4; j++)
                wmma::mma_sync(acc[i][j], af[i], bf[j], acc[i][j]);
    }
    __syncthreads();
    #pragma unroll
    for (int i = 0; i < 2; i++)
        #pragma unroll
        for (int j = 0; j < 4; j++)
            wmma::store_matrix_sync(&Cs[wm * 32 + i * 16][wn * 64 + j * 16],
                                    acc[i][j], 132, wmma::mem_row_major);
    __syncthreads();
    // fp16 feature store
    for (int c = tx; c < 128 * 32; c += 256) {
        int r = c >> 5, c4 = (c & 31) << 2;
        float4 v = *(float4*)&Cs[r][c4];
        __half2 h0 = __floats2half2_rn(v.x, v.y);
        __half2 h1 = __floats2half2_rn(v.z, v.w);
        uint2 u;
        u.x = *(unsigned int*)&h0;
        u.y = *(unsigned int*)&h1;
        *(uint2*)&g_h1h[(size_t)(rowBase + r) * F1 + colBase + c4] = u;
    }
    // fused alpha: 256 threads = (128 rows) x (2 heads in this block)
    {
        int r = tx >> 1, hl = tx & 1;
        int node = rowBase + r;
        int head = blockIdx.y * 2 + hl;
        if (node < NN) {
            const float* arow = a_src + head * 64;
            const float* drow = a_dst + head * 64;
            float s = 0.f, d = 0.f;
            #pragma unroll 8
            for (int c = 0; c < 64; c++) {
                float v = Cs[r][hl * 64 + c];
                s = fmaf(v, arow[c], s);
                d = fmaf(v, drow[c], d);
            }
            g_as1[node * 4 + head] = s;
            g_ad1[node * 4 + head] = d;
        }
    }
}

// -------- WMMA GEMM2 + fused alpha2 --------
__global__ __launch_bounds__(256)
void hgemm2_kernel(const float* __restrict__ a_src, const float* __restrict__ a_dst) {
    __shared__ __align__(16) char smem[53248];
    __half (*As)[136] = reinterpret_cast<__half(*)[136]>(smem);
    __half (*Bs)[72] = reinterpret_cast<__half(*)[72]>(smem + 34816);
    float (*Cs)[68] = reinterpret_cast<float(*)[68]>(smem);
    const int tx = threadIdx.x;
    const int rowBase = blockIdx.x * 128;

    const int warp = tx >> 5;
    const int wm = warp >> 1;
    const int wn = warp & 1;
    wmma::fragment<wmma::accumulator, 16, 16, 16, float> acc[2][2];
    #pragma unroll
    for (int i = 0; i < 2; i++)
        #pragma unroll
        for (int j = 0; j < 2; j++) wmma::fill_fragment(acc[i][j], 0.f);

    for (int t = 0; t < 2; t++) {
        const int kBase = t * 128;
        for (int c = tx; c < 128 * 16; c += 256) {
            int r = c >> 4, c8 = (c & 15) << 3;
            *(uint4*)&As[r][c8] =
                *(const uint4*)&g_out1h[(size_t)(rowBase + r) * F1 + kBase + c8];
        }
        for (int c = tx; c < 128 * 8; c += 256) {
            int r = c >> 3, c8 = (c & 7) << 3;
            *(uint4*)&Bs[r][c8] = *(const uint4*)&g_w2h[(size_t)(kBase + r) * F2 + c8];
        }
        __syncthreads();
        #pragma unroll
        for (int k0 = 0; k0 < 128; k0 += 16) {
            wmma::fragment<wmma::matrix_a, 16, 16, 16, __half, wmma::row_major> af[2];
            wmma::fragment<wmma::matrix_b, 16, 16, 16, __half, wmma::row_major> bf[2];
            #pragma unroll
            for (int i = 0; i < 2; i++)
                wmma::load_matrix_sync(af[i], &As[wm * 32 + i * 16][k0], 136);
            #pragma unroll
            for (int j = 0; j < 2; j++)
                wmma::load_matrix_sync(bf[j], &Bs[k0][wn * 32 + j * 16], 72);
            #pragma unroll
            for (int i = 0; i < 2; i++)
                #pragma unroll
                for (int j = 0; j < 2; j++)
                    wmma::mma_sync(acc[i][j], af[i], bf[j], acc[i][j]);
        }
        __syncthreads();
    }
    #pragma unroll
    for (int i = 0; i < 2; i++)
        #pragma unroll
        for (int j = 0; j < 2; j++)
            wmma::store_matrix_sync(&Cs[wm * 32 + i * 16][wn * 32 + j * 16],
                                    acc[i][j], 68, wmma::mem_row_major);
    __syncthreads();
    for (int c = tx; c < 128 * 16; c += 256) {
        int r = c >> 4, c4 = (c & 15) << 2;
        float4 v = *(float4*)&Cs[r][c4];
        __half2 h0 = __floats2half2_rn(v.x, v.y);
        __half2 h1 = __floats2half2_rn(v.z, v.w);
        uint2 u;
        u.x = *(unsigned int*)&h0;
        u.y = *(unsigned int*)&h1;
        *(uint2*)&g_h2h[(size_t)(rowBase + r) * F2 + c4] = u;
    }
    // fused alpha2: threads 0..127 = rows
    if (tx < 128) {
        int node = rowBase + tx;
        if (node < NN) {
            float s = 0.f, d = 0.f;
            #pragma unroll 8
            for (int c = 0; c < 64; c++) {
                float v = Cs[tx][c];
                s = fmaf(v, a_src[c], s);
                d = fmaf(v, a_dst[c], d);
            }
            g_as2[node] = s;
            g_ad2[node] = d;
        }
    }
}

// ---------- edge softmax layer 1: one warp per dst, 4 heads x 8 lanes ----------
__global__ __launch_bounds__(256)
void escore1_kernel() {
    int w = (blockIdx.x * blockDim.x + threadIdx.x) >> 5;
    if (w >= NN) return;
    int lane = threadIdx.x & 31;
    int h = lane >> 3, sl = lane & 7;
    int beg = g_rowptr[w], end = g_rowptr[w + 1];
    float adv = g_ad1[w * 4 + h];

    float m = -1e30f;
    for (int i = beg + sl; i < end; i += 8)
        m = fmaxf(m, lrelu(g_as1[g_csrsrc[i] * 4 + h] + adv));
    #pragma unroll
    for (int o = 4; o > 0; o >>= 1)
        m = fmaxf(m, __shfl_xor_sync(0xffffffffu, m, o, 8));

    float den = 0.f;
    for (int i = beg + sl; i < end; i += 8) {
        float p = __expf(lrelu(g_as1[g_csrsrc[i] * 4 + h] + adv) - m);
        den += p;
        g_p1[(long long)i * 4 + h] = p;
    }
    #pragma unroll
    for (int o = 4; o > 0; o >>= 1)
        den += __shfl_xor_sync(0xffffffffu, den, o, 8);
    if (sl == 0) g_den1[w * 4 + h] = den;
}

// ---------- edge softmax layer 2: one warp per dst ----------
__global__ __launch_bounds__(256)
void escore2_kernel() {
    int w = (blockIdx.x * blockDim.x + threadIdx.x) >> 5;
    if (w >= NN) return;
    int lane = threadIdx.x & 31;
    int beg = g_rowptr[w], end = g_rowptr[w + 1];
    float adv = g_ad2[w];

    float m = -1e30f;
    for (int i = beg + lane; i < end; i += 32)
        m = fmaxf(m, lrelu(g_as2[g_csrsrc[i]] + adv));
    #pragma unroll
    for (int o = 16; o > 0; o >>= 1)
        m = fmaxf(m, __shfl_xor_sync(0xffffffffu, m, o));

    float den = 0.f;
    for (int i = beg + lane; i < end; i += 32) {
        float p = __expf(lrelu(g_as2[g_csrsrc[i]] + adv) - m);
        den += p;
        g_p2[i] = p;
    }
    #pragma unroll
    for (int o = 16; o > 0; o >>= 1)
        den += __shfl_xor_sync(0xffffffffu, den, o);
    if (lane == 0) g_den2[w] = den;
}

// ------- layer 1 aggregation: pure gather+fma (p precomputed), 64 thr/dst -----
__global__ __launch_bounds__(64)
void agg1_kernel(const float* __restrict__ b1) {
    int d = blockIdx.x;
    int t = threadIdx.x;
    int h = t >> 4;
    int beg = g_rowptr[d], end = g_rowptr[d + 1];
    float inv = 1.f / (g_den1[d * 4 + h] + 1e-16f);

    const uint2* __restrict__ h1v = (const uint2*)g_h1h;
    float ax = 0.f, ay = 0.f, az = 0.f, aw = 0.f;
    int i = beg;
    for (; i + 1 < end; i += 2) {
        int s0 = g_csrsrc[i], s1 = g_csrsrc[i + 1];
        float p0 = g_p1[(long long)i * 4 + h];
        float p1 = g_p1[(long long)(i + 1) * 4 + h];
        uint2 r0 = h1v[(size_t)s0 * 64 + t];
        uint2 r1 = h1v[(size_t)s1 * 64 + t];
        float2 f0a = __half22float2(*(__half2*)&r0.x);
        float2 f0b = __half22float2(*(__half2*)&r0.y);
        float2 f1a = __half22float2(*(__half2*)&r1.x);
        float2 f1b = __half22float2(*(__half2*)&r1.y);
        ax = fmaf(p0, f0a.x, ax); ax = fmaf(p1, f1a.x, ax);
        ay = fmaf(p0, f0a.y, ay); ay = fmaf(p1, f1a.y, ay);
        az = fmaf(p0, f0b.x, az); az = fmaf(p1, f1b.x, az);
        aw = fmaf(p0, f0b.y, aw); aw = fmaf(p1, f1b.y, aw);
    }
    if (i < end) {
        int s0 = g_csrsrc[i];
        float p0 = g_p1[(long long)i * 4 + h];
        uint2 r0 = h1v[(size_t)s0 * 64 + t];
        float2 f0a = __half22float2(*(__half2*)&r0.x);
        float2 f0b = __half22float2(*(__half2*)&r0.y);
        ax = fmaf(p0, f0a.x, ax); ay = fmaf(p0, f0a.y, ay);
        az = fmaf(p0, f0b.x, az); aw = fmaf(p0, f0b.y, aw);
    }
    float4 bv = ((const float4*)b1)[t];
    float ox = fmaxf(ax * inv + bv.x, 0.f);
    float oy = fmaxf(ay * inv + bv.y, 0.f);
    float oz = fmaxf(az * inv + bv.z, 0.f);
    float ow = fmaxf(aw * inv + bv.w, 0.f);
    __half2 ha = __floats2half2_rn(ox, oy);
    __half2 hb = __floats2half2_rn(oz, ow);
    uint2 u;
    u.x = *(unsigned int*)&ha;
    u.y = *(unsigned int*)&hb;
    ((uint2*)g_out1h)[(size_t)d * 64 + t] = u;
}

// ------- layer 2 aggregation: pure gather+fma, 4 dsts per 64-thread block -----
__global__ __launch_bounds__(64)
void agg2_kernel(const float* __restrict__ b2, float* __restrict__ out) {
    int t = threadIdx.x;
    int g = t >> 4;
    int l = t & 15;
    int d = blockIdx.x * 4 + g;
    if (d >= NN) return;
    int beg = g_rowptr[d], end = g_rowptr[d + 1];
    float inv = 1.f / (g_den2[d] + 1e-16f);

    const uint2* __restrict__ h2v = (const uint2*)g_h2h;
    float ax = 0.f, ay = 0.f, az = 0.f, aw = 0.f;
    int i = beg;
    for (; i + 1 < end; i += 2) {
        int s0 = g_csrsrc[i], s1 = g_csrsrc[i + 1];
        float p0 = g_p2[i], p1 = g_p2[i + 1];
        uint2 r0 = h2v[(size_t)s0 * 16 + l];
        uint2 r1 = h2v[(size_t)s1 * 16 + l];
        float2 f0a = __half22float2(*(__half2*)&r0.x);
        float2 f0b = __half22float2(*(__half2*)&r0.y);
        float2 f1a = __half22float2(*(__half2*)&r1.x);
        float2 f1b = __half22float2(*(__half2*)&r1.y);
        ax = fmaf(p0, f0a.x, ax); ax = fmaf(p1, f1a.x, ax);
        ay = fmaf(p0, f0a.y, ay); ay = fmaf(p1, f1a.y, ay);
        az = fmaf(p0, f0b.x, az); az = fmaf(p1, f1b.x, az);
        aw = fmaf(p0, f0b.y, aw); aw = fmaf(p1, f1b.y, aw);
    }
    if (i < end) {
        int s0 = g_csrsrc[i];
        float p0 = g_p2[i];
        uint2 r0 = h2v[(size_t)s0 * 16 + l];
        float2 f0a = __half22float2(*(__half2*)&r0.x);
        float2 f0b = __half22float2(*(__half2*)&r0.y);
        ax = fmaf(p0, f0a.x, ax); ay = fmaf(p0, f0a.y, ay);
        az = fmaf(p0, f0b.x, az); aw = fmaf(p0, f0b.y, aw);
    }
    float4 bv = ((const float4*)b2)[l];
    float4 o;
    o.x = ax * inv + bv.x;
    o.y = ay * inv + bv.y;
    o.z = az * inv + bv.z;
    o.w = aw * inv + bv.w;
    ((float4*)out)[(size_t)d * 16 + l] = o;
}

// ---------------- launch ----------------
extern "C" void kernel_launch(void* const* d_in, const int* in_sizes, int n_in,
                              void* d_out, int out_size) {
    const float* x      = (const float*)d_in[0];
    const int*   edge   = (const int*)d_in[1];   // int32 (JAX x64 disabled)
    const float* W1     = (const float*)d_in[2];
    const float* a_src1 = (const float*)d_in[3];
    const float* a_dst1 = (const float*)d_in[4];
    const float* b1     = (const float*)d_in[5];
    const float* W2     = (const float*)d_in[6];
    const float* a_src2 = (const float*)d_in[7];
    const float* a_dst2 = (const float*)d_in[8];
    const float* b2     = (const float*)d_in[9];
    float* out = (float*)d_out;

    k_prep<<<(RTOT + 255) / 256, 256>>>(x, W1, W2);          // idx 0
    k_count<<<(NE + 255) / 256, 256>>>(edge);                // idx 1
    k_scan_a<<<NBLK, 1024>>>();                              // idx 2

    // idx 3: GEMM1 + fused alpha1 (profiled slot)
    {
        dim3 grid(NNP / 128, F1 / 128);
        hgemm1_kernel<<<grid, 256>>>(a_src1, a_dst1);
    }

    k_scan_b<<<1, 32>>>();                                   // idx 4
    k_scan_c<<<NBLK, 1024>>>();                              // idx 5
    k_scatter<<<(NT + 255) / 256, 256>>>(edge);              // idx 6
    escore1_kernel<<<(NN * 32 + 255) / 256, 256>>>();        // idx 7
    agg1_kernel<<<NN, 64>>>(b1);                             // idx 8
    hgemm2_kernel<<<NNP / 128, 256>>>(a_src2, a_dst2);       // idx 9
    escore2_kernel<<<(NN * 32 + 255) / 256, 256>>>();        // idx 10
    agg2_kernel<<<(NN + 3) / 4, 64>>>(b2, out);              // idx 11
}